// round 17
// baseline (speedup 1.0000x reference)
#include <cuda_runtime.h>
#include <cuda_fp16.h>
#include <math_constants.h>

#define HH 512
#define WW 512
#define BB 16
// window p=35, pad=17
// loss = mean(erosion_35x35(min_c x)) - 1   (erosion = separable min filter)

// Stage-0 output: channel-min of x, [B][H][W/2] half2  (8.4MB)
__device__ __align__(16) __half2 g_min[BB * HH * WW / 2];
// Intermediate: vertically eroded field, [B][H][W/2], half2 packs (w, w+1)
__device__ __align__(16) __half2 g_t2[BB * HH * WW / 2];
// Per-block partial sums from kernel 2 (1024 blocks)
__device__ float g_partial[1024];

// ---------------------------------------------------------------------------
// Kernel 0: PURE STREAMING channel-min (fp32 x3 -> fp16). No smem, no
// barriers: 6 independent LDG.128 + 1 STG.128 per thread, full occupancy.
// Thread j handles 8 consecutive w at (b, h). grid = 2048 x 256.
// ---------------------------------------------------------------------------
__global__ __launch_bounds__(256) void k0_cmin(const float* __restrict__ x) {
    const int j  = blockIdx.x * 256 + threadIdx.x;    // 0..524287
    const int w8 = (j & 63) * 8;
    const int h  = (j >> 6) & 511;
    const int b  = j >> 15;

    const float* p0 = x + (size_t)b * 3 * HH * WW + (size_t)h * WW + w8;
    const float4* q0 = (const float4*)p0;
    const float4* q1 = (const float4*)(p0 + HH * WW);
    const float4* q2 = (const float4*)(p0 + 2 * HH * WW);
    float4 a0 = q0[0], b0 = q0[1];
    float4 a1 = q1[0], b1 = q1[1];
    float4 a2 = q2[0], b2 = q2[1];

    float4 m0, m1;
    m0.x = fminf(a0.x, fminf(a1.x, a2.x));
    m0.y = fminf(a0.y, fminf(a1.y, a2.y));
    m0.z = fminf(a0.z, fminf(a1.z, a2.z));
    m0.w = fminf(a0.w, fminf(a1.w, a2.w));
    m1.x = fminf(b0.x, fminf(b1.x, b2.x));
    m1.y = fminf(b0.y, fminf(b1.y, b2.y));
    m1.z = fminf(b0.z, fminf(b1.z, b2.z));
    m1.w = fminf(b0.w, fminf(b1.w, b2.w));

    __half2 h0 = __floats2half2_rn(m0.x, m0.y);
    __half2 h1 = __floats2half2_rn(m0.z, m0.w);
    __half2 h2 = __floats2half2_rn(m1.x, m1.y);
    __half2 h3 = __floats2half2_rn(m1.z, m1.w);
    uint4 o = make_uint4(*(unsigned*)&h0, *(unsigned*)&h1,
                         *(unsigned*)&h2, *(unsigned*)&h3);
    *(uint4*)&g_min[(size_t)j * 4] = o;
}

// ---------------------------------------------------------------------------
// Kernel 1: vertical min-filter, R12's verified geometry/chains, but the
// tile now loads fp16 g_min (16.8MB L2-hot total, 6 uint4/thread) instead
// of 50MB fp32. Block = 256 thr (8 warps all load; chains on ty<4).
// grid = (W/64, B, 4) = 512 blocks.
// ---------------------------------------------------------------------------
__global__ __launch_bounds__(256) void k1_vert() {
    __shared__ __half2 sm[174 * 32];

    const int tx  = threadIdx.x;
    const int ty  = threadIdx.y;              // 0..7
    const int tid = ty * 32 + tx;
    const int wc0 = blockIdx.x * 64;
    const int b   = blockIdx.y;
    const int z   = blockIdx.z;
    const int r0  = z * 140;                 // 4 chunks * 35 rows per z-group

    // Tile load: rows [r0-17, r0+157) x 32 half2; 174*8 = 1392 uint4.
    const __half2* mb = g_min + (size_t)b * HH * (WW / 2) + (wc0 >> 1);
    for (int j = tid; j < 1392; j += 256) {
        int r  = j >> 3;
        int c  = j & 7;                       // uint4 slot (8 per row)
        int gh = r0 - 17 + r;
        uint4 v = make_uint4(0x7C007C00u, 0x7C007C00u, 0x7C007C00u, 0x7C007C00u);
        if ((unsigned)gh < HH)
            v = ((const uint4*)(mb + (size_t)gh * (WW / 2)))[c];
        *(uint4*)&sm[r * 32 + c * 4] = v;     // STS.128, conflict-free
    }
    __syncthreads();

    // Chains: warps ty<4 only (chunk = z*4+ty).
    if (ty >= 4) return;
    const int c    = z * 4 + ty;
    const int base = 35 * c;
    if (base >= HH) return;
    const int lb = 35 * ty + 17;
    const __half2 HINF = __float2half2_rn(CUDART_INF_F);

    // Pass 1: suffix minima (segment reset at k==35)
    __half2 S[35];
    __half2 run = HINF;
    #pragma unroll
    for (int k = 0; k < 52; k++) {
        if (k == 35) run = HINF;
        run = __hmin2(run, sm[(lb + 34 - k) * 32 + tx]);
        if (k >= 17) S[51 - k] = run;
    }

    // Pass 2: prefix minima, combine + store on the fly
    run = HINF;
    const size_t ob = (size_t)b * HH;
    const int wcol = (wc0 >> 1) + tx;
    #pragma unroll
    for (int k = 0; k < 52; k++) {
        if (k == 35) run = HINF;
        run = __hmin2(run, sm[(lb + k) * 32 + tx]);
        if (k >= 17) {
            int i = base + k - 17;
            if (i < HH)
                g_t2[(ob + i) * (WW / 2) + wcol] = __hmin2(S[k - 17], run);
        }
    }
}

// ---------------------------------------------------------------------------
// Kernel 2: horizontal min-filter in PAIR DOMAIN, chunk length 36 (verified
// round-9 math), register-resident chains: 18 independent predicated LDG.64
// per thread, then pure register suffix/prefix/combine.
// Thread (tx = chunk slot 0..15, ty = row 0..7); grid = (H/8, B).
// ---------------------------------------------------------------------------
__global__ __launch_bounds__(128) void k2_horiz() {
    __shared__ float red[128];

    const int tx  = threadIdx.x;              // chunk slot 0..15 (t = tx-1)
    const int ty  = threadIdx.y;              // row-in-tile 0..7
    const int tid = ty * 16 + tx;
    const int h0  = blockIdx.x * 8;
    const int b   = blockIdx.y;
    const __half2 HINF2 = __float2half2_rn(CUDART_INF_F);
    const unsigned INFU = 0x7C007C00u;

    const int t = tx - 1;                     // -1..14
    const __half2* rowp = g_t2 + (size_t)(b * HH + h0 + ty) * (WW / 2);

    // Load chunk t (pairs [18t, 18t+18)) and chunk t+1 into registers.
    __half2 ct[18], dt[18];
    #pragma unroll
    for (int j = 0; j < 9; j++) {
        int p0 = 18 * t + 2 * j;
        uint2 v = make_uint2(INFU, INFU);
        if ((unsigned)p0 < 256u) v = *(const uint2*)(rowp + p0);
        ct[2 * j]     = *(__half2*)&v.x;
        ct[2 * j + 1] = *(__half2*)&v.y;
    }
    #pragma unroll
    for (int j = 0; j < 9; j++) {
        int p0 = 18 * (t + 1) + 2 * j;
        uint2 v = make_uint2(INFU, INFU);
        if ((unsigned)p0 < 256u) v = *(const uint2*)(rowp + p0);
        dt[2 * j]     = *(__half2*)&v.x;
        dt[2 * j + 1] = *(__half2*)&v.y;
    }

    // Backward: suffix pair-minima over chunk t
    __half2 SR[18];
    {
        __half2 run = HINF2;
        #pragma unroll
        for (int u = 17; u >= 0; u--) {
            run = __hmin2(run, ct[u]);
            SR[u] = run;
        }
    }

    // Forward over chunk t+1 + parity combine + accumulate
    __half2 hacc = __float2half2_rn(0.0f);
    __half2 Rp  = HINF2;                      // R[n-1]
    __half2 HPp = HINF2;                      // hmin(R[n-1]) broadcast
    const int obase = 36 * t + 18;
    #pragma unroll
    for (int n = 0; n < 18; n++) {
        __half2 v  = dt[n];
        __half2 Rc = __hmin2(Rp, v);          // R[n]
        __half2 srn = (n < 17) ? SR[n + 1] : HINF2;
        unsigned srnu = *(unsigned*)&srn;
        unsigned swp  = __byte_perm(srnu, srnu, 0x1032);
        __half2 hs = __hmin2(srn, *(__half2*)&swp);   // H_S[n+1] broadcast
        unsigned sru = *(unsigned*)&SR[n];
        unsigned Rcu = *(unsigned*)&Rc;
        unsigned Rpu = *(unsigned*)&Rp;
        unsigned HPu = *(unsigned*)&HPp;
        unsigned Au = __byte_perm(sru, Rcu, 0x5432);  // (SR[n].hi, Rc.lo)
        unsigned Bu = __byte_perm(HPu, Rpu, 0x7610);  // (HPp,      Rp.hi)
        __half2 o = __hmin2(__hmin2(*(__half2*)&Au, *(__half2*)&Bu), hs);
        if ((unsigned)(obase + 2 * n) < 512u)
            hacc = __hadd2(hacc, o);
        unsigned rs = __byte_perm(Rcu, Rcu, 0x1032);
        HPp = __hmin2(Rc, *(__half2*)&rs);    // hmin(R[n]) broadcast
        Rp = Rc;
    }
    float2 e2 = __half22float2(hacc);
    float acc = e2.x + e2.y;

    // Deterministic in-block reduction -> one partial per block
    red[tid] = acc;
    __syncthreads();
    #pragma unroll
    for (int s = 64; s > 0; s >>= 1) {
        if (tid < s) red[tid] += red[tid + s];
        __syncthreads();
    }
    if (tid == 0) g_partial[b * 64 + blockIdx.x] = red[0];
}

// ---------------------------------------------------------------------------
// Kernel 3: final reduction of 1024 partials; loss = mean(erosion) - 1.
// ---------------------------------------------------------------------------
__global__ void k3_final(float* __restrict__ out) {
    __shared__ float red[512];
    int tid = threadIdx.x;
    red[tid] = g_partial[tid] + g_partial[tid + 512];
    __syncthreads();
    #pragma unroll
    for (int s = 256; s > 0; s >>= 1) {
        if (tid < s) red[tid] += red[tid + s];
        __syncthreads();
    }
    if (tid == 0) out[0] = red[0] * (1.0f / 4194304.0f) - 1.0f;
}

extern "C" void kernel_launch(void* const* d_in, const int* in_sizes, int n_in,
                              void* d_out, int out_size) {
    const float* x = (const float*)d_in[0];
    float* out = (float*)d_out;

    k0_cmin<<<2048, 256>>>(x);
    k1_vert<<<dim3(WW / 64, BB, 4), dim3(32, 8)>>>();
    k2_horiz<<<dim3(HH / 8, BB), dim3(16, 8)>>>();
    k3_final<<<1, 512>>>(out);
}